// round 12
// baseline (speedup 1.0000x reference)
#include <cuda_runtime.h>
#include <cuda_bf16.h>
#include <stdint.h>

#define BATCH   8
#define NNODE   1024
#define CH      256
#define NEDGE   16384
#define BIGN    (BATCH * NNODE)          // 8192
#define WPR     32                       // bitmap words per row
#define CSRW    48                       // padded CSR width per row (ints)

// ---- scratch (__device__ globals; allocation-free rule) ----
__device__ __align__(128) unsigned g_adj[BIGN * WPR];    // 1 MB adjacency bitmap
__device__ __align__(128) float    g_dinv[BIGN];
__device__ __align__(128) float    g_ys[BIGN * CH];      // ys = dinv * (x @ W^T)
__device__ __align__(128) int      g_csr[BIGN * CSRW];   // neighbor lists + sentinel pad
__device__ __align__(128) int      g_cnt[BIGN];
// packed bf16 hi/lo tiles, SW128-swizzled, contiguous per (tile, kchunk):
// x: [64 m-tiles(128 rows)][4 chunks][hi 16KB | lo 16KB] -> 32KB units
// w: [2 n-halves(128 rows)][4 chunks][hi 16KB | lo 16KB] -> 32KB units
__device__ __align__(128) char     g_xpk[64 * 4 * 32768];   // 8 MB
__device__ __align__(128) char     g_wpk[2 * 4 * 32768];    // 256 KB

// ================================================================ helpers
__device__ __forceinline__ uint32_t s2u(const void* p) {
    uint32_t a;
    asm("{ .reg .u64 t; cvta.to.shared.u64 t, %1; cvt.u32.u64 %0, t; }" : "=r"(a) : "l"(p));
    return a;
}
__device__ __forceinline__ uint32_t split2(float2 f, uint32_t& lo) {
    uint32_t hi;
    asm("cvt.rn.bf16x2.f32 %0, %1, %2;" : "=r"(hi) : "f"(f.y), "f"(f.x));
    float hx = __uint_as_float(hi << 16);
    float hy = __uint_as_float(hi & 0xffff0000u);
    asm("cvt.rn.bf16x2.f32 %0, %1, %2;" : "=r"(lo) : "f"(f.y - hy), "f"(f.x - hx));
    return hi;
}
__device__ __forceinline__ void mma16816(float* c, const uint32_t* a, const uint32_t* b) {
    asm volatile(
        "mma.sync.aligned.m16n8k16.row.col.f32.bf16.bf16.f32 "
        "{%0,%1,%2,%3}, {%4,%5,%6,%7}, {%8,%9}, {%0,%1,%2,%3};"
        : "+f"(c[0]), "+f"(c[1]), "+f"(c[2]), "+f"(c[3])
        : "r"(a[0]), "r"(a[1]), "r"(a[2]), "r"(a[3]), "r"(b[0]), "r"(b[1]));
}
__device__ __forceinline__ void ldsm4(uint32_t* r, uint32_t addr) {
    asm volatile("ldmatrix.sync.aligned.m8n8.x4.shared.b16 {%0,%1,%2,%3}, [%4];"
                 : "=r"(r[0]), "=r"(r[1]), "=r"(r[2]), "=r"(r[3]) : "r"(addr));
}
__device__ __forceinline__ void mbar_wait(uint32_t addr, uint32_t parity) {
    asm volatile(
        "{\n\t.reg .pred P1;\n"
        "WL%=:\n\t"
        "mbarrier.try_wait.parity.acquire.cta.shared::cta.b64 P1, [%0], %1, 0x989680;\n\t"
        "@P1 bra WD%=;\n\t"
        "bra WL%=;\n"
        "WD%=:\n\t}"
        :: "r"(addr), "r"(parity) : "memory");
}
__device__ __forceinline__ void bulk_cp(uint32_t sdst, const void* gsrc, uint32_t bytes,
                                        uint32_t mb) {
    asm volatile(
        "{ .reg .u64 g; cvta.to.global.u64 g, %1;\n\t"
        "cp.async.bulk.shared::cta.global.mbarrier::complete_tx::bytes [%0], [g], %2, [%3]; }"
        :: "r"(sdst), "l"(gsrc), "r"(bytes), "r"(mb) : "memory");
}

// ================================================================ prep v2: pack x,W (bf16 hi/lo, swizzled) + zero bitmap
// one thread = 8 consecutive channels of one row: 2x LDG.128 -> 2x STG.128
__global__ void __launch_bounds__(256) k_prep(const float* __restrict__ x,
                                              const float* __restrict__ Wm)
{
    int t = blockIdx.x * 256 + threadIdx.x;          // 262144 threads
    {
        int row = t >> 5, s = t & 31, ch = s * 8;
        const float4* xp = (const float4*)(x + row * CH + ch);
        float4 v0 = xp[0], v1 = xp[1];
        uint4 hv, lv;
        hv.x = split2(make_float2(v0.x, v0.y), lv.x);
        hv.y = split2(make_float2(v0.z, v0.w), lv.y);
        hv.z = split2(make_float2(v1.x, v1.y), lv.z);
        hv.w = split2(make_float2(v1.z, v1.w), lv.w);
        int tile = row >> 7, r = row & 127, c = ch >> 6, cc = ch & 63;
        uint32_t off = (uint32_t)((tile * 4 + c) * 32768)
                     + ((uint32_t)(r * 128 + cc * 2) ^ ((uint32_t)(r & 7) << 4));
        *(uint4*)(g_xpk + off)         = hv;
        *(uint4*)(g_xpk + off + 16384) = lv;
    }
    if (t < CH * 32) {                                // 8192 threads for W
        int row = t >> 5, s = t & 31, ch = s * 8;
        const float4* wp = (const float4*)(Wm + row * CH + ch);
        float4 v0 = wp[0], v1 = wp[1];
        uint4 hv, lv;
        hv.x = split2(make_float2(v0.x, v0.y), lv.x);
        hv.y = split2(make_float2(v0.z, v0.w), lv.y);
        hv.z = split2(make_float2(v1.x, v1.y), lv.z);
        hv.w = split2(make_float2(v1.z, v1.w), lv.w);
        int hf = row >> 7, r = row & 127, c = ch >> 6, cc = ch & 63;
        uint32_t off = (uint32_t)((hf * 4 + c) * 32768)
                     + ((uint32_t)(r * 128 + cc * 2) ^ ((uint32_t)(r & 7) << 4));
        *(uint4*)(g_wpk + off)         = hv;
        *(uint4*)(g_wpk + off + 16384) = lv;
    }
    if (t < BIGN * WPR / 4)
        ((uint4*)g_adj)[t] = make_uint4(0u, 0u, 0u, 0u);
}

// ================================================================ edge scatter (dedup via bitmap)
__global__ void k_scatter(const int* __restrict__ ei) {
    int t = blockIdx.x * blockDim.x + threadIdx.x;
    if (t >= NEDGE * BATCH) return;
    int src = ei[t];
    int dst = ei[NEDGE * BATCH + t];
    int b   = t & (BATCH - 1);
    int row = b * NNODE + src;
    atomicOr(&g_adj[row * WPR + (dst >> 5)], 1u << (dst & 31));
}

// ================================================================ degree -> dinv + CSR extraction (+sentinel pad to 16)
__global__ void __launch_bounds__(256) k_deg() {
    int tid  = threadIdx.x;
    int lane = tid & 31;
    int r    = blockIdx.x * 8 + (tid >> 5);

    unsigned w = g_adj[r * WPR + lane];
    int c = __popc(w);
    int s = c;
    #pragma unroll
    for (int o = 1; o < 32; o <<= 1) {
        int v = __shfl_up_sync(0xffffffffu, s, o);
        if (lane >= o) s += v;
    }
    int excl  = s - c;
    int total = __shfl_sync(0xffffffffu, s, 31);
    if (lane == 0) {
        g_dinv[r] = rsqrtf((float)(total + 1));    // +1 self loop (eye)
        g_cnt[r]  = total;
    }
    int i = 0;
    while (w) {
        int b = __ffs(w) - 1;
        w &= w - 1;
        if (excl + i < CSRW) g_csr[r * CSRW + excl + i] = lane * 32 + b;
        i++;
    }
    // sentinel-pad to a multiple of 16 (sentinel 1024 -> zero smem row)
    int padend = (total + 15) & ~15;
    if (padend > CSRW) padend = CSRW;
    for (int p = total + lane; p < padend; p += 32)
        g_csr[r * CSRW + p] = NNODE;
}

// ================================================================ bulk-copy pipelined HMMA GEMM: ys = dinv * (x @ W^T)
// CTA 128x128 (mt, half), 512 threads (16 warps 4x4), warp tile 32x32.
// K chunks of 64 staged by cp.async.bulk (2 x 32KB per chunk), double buffered.
#define GSM 131072

__device__ __forceinline__ void issue_chunk(uint32_t sbuf, uint32_t mb, int mt, int hf, int c) {
    asm volatile("mbarrier.arrive.expect_tx.shared.b64 _, [%0], %1;"
                 :: "r"(mb), "r"(65536u) : "memory");
    bulk_cp(sbuf,          g_xpk + (mt * 4 + c) * 32768, 32768u, mb);
    bulk_cp(sbuf + 32768u, g_wpk + (hf * 4 + c) * 32768, 32768u, mb);
}

__global__ void __launch_bounds__(512) k_gemm()
{
    extern __shared__ __align__(128) char dsm[];
    __shared__ __align__(8) unsigned long long s_mbar[2];
    uint32_t base = s2u(dsm);
    uint32_t mbar = s2u(s_mbar);

    int tid = threadIdx.x;
    int wid = tid >> 5, lane = tid & 31;
    int g = lane >> 2, tg = lane & 3;
    int wm = wid >> 2, wn = wid & 3;
    int mt = blockIdx.x, hf = blockIdx.y;

    if (tid == 0) {
        asm volatile("mbarrier.init.shared.b64 [%0], 1;" :: "r"(mbar)     : "memory");
        asm volatile("mbarrier.init.shared.b64 [%0], 1;" :: "r"(mbar + 8) : "memory");
    }
    __syncthreads();
    if (tid == 0) {
        issue_chunk(base,          mbar,     mt, hf, 0);
        issue_chunk(base + 65536u, mbar + 8, mt, hf, 1);
    }

    uint32_t lanerow = (uint32_t)((lane & 15) * 128);
    uint32_t colbase = (uint32_t)((lane >> 4) * 16);
    uint32_t xorm    = (uint32_t)((lane & 7) << 4);

    float acc[2][4][4];
    #pragma unroll
    for (int i = 0; i < 2; i++)
        #pragma unroll
        for (int j = 0; j < 4; j++)
            #pragma unroll
            for (int q = 0; q < 4; q++) acc[i][j][q] = 0.f;

    for (int c = 0; c < 4; c++) {
        uint32_t buf = base + (uint32_t)(c & 1) * 65536u;
        mbar_wait(mbar + (uint32_t)(c & 1) * 8, (uint32_t)(c >> 1));

        uint32_t abase = buf + (uint32_t)(wm * 32 * 128) + lanerow;           // hi; lo at +16384
        uint32_t bbase = buf + 32768u + (uint32_t)(wn * 32 * 128) + lanerow;

        #pragma unroll
        for (int ks = 0; ks < 4; ks++) {
            uint32_t koff = (colbase + (uint32_t)(ks * 32)) ^ xorm;
            uint32_t ah[2][4], al[2][4], bh[2][4], bl[2][4];
            #pragma unroll
            for (int mi = 0; mi < 2; mi++) {
                ldsm4(ah[mi], abase + (uint32_t)(mi * 2048) + koff);
                ldsm4(al[mi], abase + 16384u + (uint32_t)(mi * 2048) + koff);
            }
            #pragma unroll
            for (int nt = 0; nt < 2; nt++) {
                ldsm4(bh[nt], bbase + (uint32_t)(nt * 2048) + koff);
                ldsm4(bl[nt], bbase + 16384u + (uint32_t)(nt * 2048) + koff);
            }
            #pragma unroll
            for (int mi = 0; mi < 2; mi++)
                #pragma unroll
                for (int ni = 0; ni < 4; ni++) {
                    int nt = ni >> 1, sel = ni & 1;
                    uint32_t bbh[2] = { bh[nt][sel], bh[nt][sel + 2] };
                    uint32_t bbl[2] = { bl[nt][sel], bl[nt][sel + 2] };
                    mma16816(acc[mi][ni], ah[mi], bbh);
                    mma16816(acc[mi][ni], ah[mi], bbl);
                    mma16816(acc[mi][ni], al[mi], bbh);
                }
        }
        __syncthreads();                       // all warps done with this buffer
        if (c < 2 && tid == 0)
            issue_chunk(buf, mbar + (uint32_t)(c & 1) * 8, mt, hf, c + 2);
    }

    // ---- epilogue: ys = dinv[row] * acc
    int m0 = mt * 128, n0 = hf * 128;
    #pragma unroll
    for (int mi = 0; mi < 2; mi++) {
        int r = m0 + wm * 32 + mi * 16 + g;
        float d0 = g_dinv[r];
        float d1 = g_dinv[r + 8];
        #pragma unroll
        for (int ni = 0; ni < 4; ni++) {
            int ncol = n0 + wn * 32 + ni * 8 + tg * 2;
            float2 o0 = { acc[mi][ni][0] * d0, acc[mi][ni][1] * d0 };
            float2 o1 = { acc[mi][ni][2] * d1, acc[mi][ni][3] * d1 };
            *(float2*)&g_ys[r * CH + ncol]       = o0;
            *(float2*)&g_ys[(r + 8) * CH + ncol] = o1;
        }
    }
}

// ================================================================ aggregate v2 (smem gather):
// out = dinv_i*(Sum_N ys + ys_self) + bias
// grid (chunk32=8, graph=8, rowhalf=2) = 128 CTAs; 1024 threads; smem 1025x128B
#define AGG_SMEM ((NNODE + 1) * 32 * 4)

__global__ void __launch_bounds__(1024) k_aggregate(const float* __restrict__ bias,
                                                    float* __restrict__ out)
{
    extern __shared__ float sm[];                  // [1025][32]
    int t     = threadIdx.x;
    int c0    = blockIdx.x * 32;
    int gbase = blockIdx.y << 10;
    int rh    = blockIdx.z;

    // ---- stage this graph's 32-channel ys slice (coalesced: 8 lanes x 16B per row)
    {
        int l8 = t & 7;
        const float4* ysp = (const float4*)(g_ys + c0) ;
        #pragma unroll
        for (int pass = 0; pass < 8; pass++) {
            int row = pass * 128 + (t >> 3);
            float4 v = ysp[(gbase + row) * 64 + l8];
            *(float4*)&sm[row * 32 + l8 * 4] = v;
        }
    }
    if (t < 32) sm[NNODE * 32 + t] = 0.f;          // sentinel row (pad target)
    __syncthreads();

    int lane = t & 31, w = t >> 5;                 // 32 warps
    int sub = lane >> 3, l8 = lane & 7;            // 4 rows x 8 channel-lanes
    float4 bv = *(const float4*)&bias[c0 + l8 * 4];

    #pragma unroll
    for (int grp = 0; grp < 4; grp++) {
        int r    = rh * 512 + w * 16 + grp * 4 + sub;
        int grow = gbase + r;
        int cnt  = g_cnt[grow];
        float dinv = g_dinv[grow];
        const uint4* list4 = (const uint4*)&g_csr[grow * CSRW];

        float4 acc = *(const float4*)&sm[r * 32 + l8 * 4];     // self (eye) term
        int nb = (cnt + 15) >> 4;                              // 16-neighbor batches
        for (int b = 0; b < nb; b++) {
            uint4 j0 = list4[b * 4 + 0];
            uint4 j1 = list4[b * 4 + 1];
            uint4 j2 = list4[b * 4 + 2];
            uint4 j3 = list4[b * 4 + 3];
            uint32_t idx[16] = { j0.x, j0.y, j0.z, j0.w, j1.x, j1.y, j1.z, j1.w,
                                 j2.x, j2.y, j2.z, j2.w, j3.x, j3.y, j3.z, j3.w };
            #pragma unroll
            for (int q = 0; q < 16; q++) {
                float4 v = *(const float4*)&sm[idx[q] * 32 + l8 * 4];
                acc.x += v.x; acc.y += v.y; acc.z += v.z; acc.w += v.w;
            }
        }
        float4 o;
        o.x = fmaf(dinv, acc.x, bv.x);
        o.y = fmaf(dinv, acc.y, bv.y);
        o.z = fmaf(dinv, acc.z, bv.z);
        o.w = fmaf(dinv, acc.w, bv.w);
        *(float4*)&out[grow * CH + c0 + l8 * 4] = o;
    }
}

// ================================================================ launch
extern "C" void kernel_launch(void* const* d_in, const int* in_sizes, int n_in,
                              void* d_out, int out_size)
{
    const float* x    = (const float*)d_in[0];   // [8,1024,256] f32
    const int*   ei   = (const int*)  d_in[1];   // [2,16384,8] int32
    const float* Wm   = (const float*)d_in[2];   // [256,256] f32
    const float* bias = (const float*)d_in[3];   // [256] f32
    float*       out  = (float*)d_out;

    cudaFuncSetAttribute(k_gemm, cudaFuncAttributeMaxDynamicSharedMemorySize, GSM);
    cudaFuncSetAttribute(k_aggregate, cudaFuncAttributeMaxDynamicSharedMemorySize, AGG_SMEM);

    k_prep<<<BIGN * 32 / 256, 256>>>(x, Wm);
    k_scatter<<<(NEDGE * BATCH + 255) / 256, 256>>>(ei);
    k_deg<<<BIGN / 8, 256>>>();
    k_gemm<<<dim3(BIGN / 128, CH / 128), 512, GSM>>>();
    k_aggregate<<<dim3(8, 8, 2), 1024, AGG_SMEM>>>(bias, out);
}

// round 13
// speedup vs baseline: 1.1212x; 1.1212x over previous
#include <cuda_runtime.h>
#include <cuda_fp16.h>
#include <stdint.h>

#define BATCH   8
#define NNODE   1024
#define CH      256
#define NEDGE   16384
#define BIGN    (BATCH * NNODE)          // 8192
#define WPR     32                       // bitmap words per row
#define CSRW    48                       // padded CSR width per row (ints)

// ---- scratch (__device__ globals; allocation-free rule) ----
__device__ __align__(128) unsigned g_adj[BIGN * WPR];    // 1 MB adjacency bitmap
__device__ __align__(128) float    g_dinv[BIGN];
__device__ __align__(128) __half   g_ysh[BIGN * CH];     // ys = dinv*(x@W^T), fp16 (4 MB)
__device__ __align__(128) int      g_csr[BIGN * CSRW];
__device__ __align__(128) int      g_cnt[BIGN];
// packed fp16 hi/lo tiles, SW128-swizzled, contiguous per (tile, kchunk):
// x: [64 m-tiles(128 rows)][4 chunks][hi 16KB | lo 16KB] -> 32KB units
// w: [2 n-halves(128 rows)][4 chunks][hi 16KB | lo 16KB] -> 32KB units
// lo values are pre-scaled by 1024 (avoids fp16 subnormals for W residuals)
__device__ __align__(128) char     g_xpk[64 * 4 * 32768];   // 8 MB
__device__ __align__(128) char     g_wpk[2 * 4 * 32768];    // 256 KB

// ================================================================ helpers
__device__ __forceinline__ uint32_t s2u(const void* p) {
    uint32_t a;
    asm("{ .reg .u64 t; cvta.to.shared.u64 t, %1; cvt.u32.u64 %0, t; }" : "=r"(a) : "l"(p));
    return a;
}
// fp16 hi/lo split; lo scaled by 1024
__device__ __forceinline__ uint32_t split2h(float2 f, uint32_t& lo) {
    uint32_t hi;
    asm("cvt.rn.f16x2.f32 %0, %1, %2;" : "=r"(hi) : "f"(f.y), "f"(f.x));
    __half2 h = *reinterpret_cast<__half2*>(&hi);
    float2 hf = __half22float2(h);
    asm("cvt.rn.f16x2.f32 %0, %1, %2;" : "=r"(lo)
        : "f"((f.y - hf.y) * 1024.f), "f"((f.x - hf.x) * 1024.f));
    return hi;
}
__device__ __forceinline__ void mma_f32(float* c, const uint32_t* a, const uint32_t* b) {
    asm volatile(
        "mma.sync.aligned.m16n8k16.row.col.f32.f16.f16.f32 "
        "{%0,%1,%2,%3}, {%4,%5,%6,%7}, {%8,%9}, {%0,%1,%2,%3};"
        : "+f"(c[0]), "+f"(c[1]), "+f"(c[2]), "+f"(c[3])
        : "r"(a[0]), "r"(a[1]), "r"(a[2]), "r"(a[3]), "r"(b[0]), "r"(b[1]));
}
__device__ __forceinline__ void mma_f16(uint32_t* c, const uint32_t* a, const uint32_t* b) {
    asm volatile(
        "mma.sync.aligned.m16n8k16.row.col.f16.f16.f16.f16 "
        "{%0,%1}, {%2,%3,%4,%5}, {%6,%7}, {%0,%1};"
        : "+r"(c[0]), "+r"(c[1])
        : "r"(a[0]), "r"(a[1]), "r"(a[2]), "r"(a[3]), "r"(b[0]), "r"(b[1]));
}
__device__ __forceinline__ void ldsm4(uint32_t* r, uint32_t addr) {
    asm volatile("ldmatrix.sync.aligned.m8n8.x4.shared.b16 {%0,%1,%2,%3}, [%4];"
                 : "=r"(r[0]), "=r"(r[1]), "=r"(r[2]), "=r"(r[3]) : "r"(addr));
}
__device__ __forceinline__ void mbar_wait(uint32_t addr, uint32_t parity) {
    asm volatile(
        "{\n\t.reg .pred P1;\n"
        "WL%=:\n\t"
        "mbarrier.try_wait.parity.acquire.cta.shared::cta.b64 P1, [%0], %1, 0x989680;\n\t"
        "@P1 bra WD%=;\n\t"
        "bra WL%=;\n"
        "WD%=:\n\t}"
        :: "r"(addr), "r"(parity) : "memory");
}
__device__ __forceinline__ void bulk_cp(uint32_t sdst, const void* gsrc, uint32_t bytes,
                                        uint32_t mb) {
    asm volatile(
        "{ .reg .u64 g; cvta.to.global.u64 g, %1;\n\t"
        "cp.async.bulk.shared::cta.global.mbarrier::complete_tx::bytes [%0], [g], %2, [%3]; }"
        :: "r"(sdst), "l"(gsrc), "r"(bytes), "r"(mb) : "memory");
}

// ================================================================ prep: pack x,W (fp16 hi/lo, swizzled) + zero bitmap
// one thread = 8 consecutive channels of one row: 2x LDG.128 -> 2x STG.128
__global__ void __launch_bounds__(256) k_prep(const float* __restrict__ x,
                                              const float* __restrict__ Wm)
{
    int t = blockIdx.x * 256 + threadIdx.x;          // 262144 threads
    {
        int row = t >> 5, s = t & 31, ch = s * 8;
        const float4* xp = (const float4*)(x + row * CH + ch);
        float4 v0 = xp[0], v1 = xp[1];
        uint4 hv, lv;
        hv.x = split2h(make_float2(v0.x, v0.y), lv.x);
        hv.y = split2h(make_float2(v0.z, v0.w), lv.y);
        hv.z = split2h(make_float2(v1.x, v1.y), lv.z);
        hv.w = split2h(make_float2(v1.z, v1.w), lv.w);
        int tile = row >> 7, r = row & 127, c = ch >> 6, cc = ch & 63;
        uint32_t off = (uint32_t)((tile * 4 + c) * 32768)
                     + ((uint32_t)(r * 128 + cc * 2) ^ ((uint32_t)(r & 7) << 4));
        *(uint4*)(g_xpk + off)         = hv;
        *(uint4*)(g_xpk + off + 16384) = lv;
    }
    if (t < CH * 32) {                                // 8192 threads for W
        int row = t >> 5, s = t & 31, ch = s * 8;
        const float4* wp = (const float4*)(Wm + row * CH + ch);
        float4 v0 = wp[0], v1 = wp[1];
        uint4 hv, lv;
        hv.x = split2h(make_float2(v0.x, v0.y), lv.x);
        hv.y = split2h(make_float2(v0.z, v0.w), lv.y);
        hv.z = split2h(make_float2(v1.x, v1.y), lv.z);
        hv.w = split2h(make_float2(v1.z, v1.w), lv.w);
        int hf = row >> 7, r = row & 127, c = ch >> 6, cc = ch & 63;
        uint32_t off = (uint32_t)((hf * 4 + c) * 32768)
                     + ((uint32_t)(r * 128 + cc * 2) ^ ((uint32_t)(r & 7) << 4));
        *(uint4*)(g_wpk + off)         = hv;
        *(uint4*)(g_wpk + off + 16384) = lv;
    }
    if (t < BIGN * WPR / 4)
        ((uint4*)g_adj)[t] = make_uint4(0u, 0u, 0u, 0u);
}

// ================================================================ edge scatter (dedup via bitmap)
__global__ void k_scatter(const int* __restrict__ ei) {
    int t = blockIdx.x * blockDim.x + threadIdx.x;
    if (t >= NEDGE * BATCH) return;
    int src = ei[t];
    int dst = ei[NEDGE * BATCH + t];
    int b   = t & (BATCH - 1);
    int row = b * NNODE + src;
    atomicOr(&g_adj[row * WPR + (dst >> 5)], 1u << (dst & 31));
}

// ================================================================ degree -> dinv + CSR extraction
__global__ void __launch_bounds__(256) k_deg() {
    int tid  = threadIdx.x;
    int lane = tid & 31;
    int r    = blockIdx.x * 8 + (tid >> 5);

    unsigned w = g_adj[r * WPR + lane];
    int c = __popc(w);
    int s = c;
    #pragma unroll
    for (int o = 1; o < 32; o <<= 1) {
        int v = __shfl_up_sync(0xffffffffu, s, o);
        if (lane >= o) s += v;
    }
    int excl  = s - c;
    int total = __shfl_sync(0xffffffffu, s, 31);
    if (lane == 0) {
        g_dinv[r] = rsqrtf((float)(total + 1));    // +1 self loop (eye)
        g_cnt[r]  = total;
    }
    int i = 0;
    while (w) {
        int b = __ffs(w) - 1;
        w &= w - 1;
        if (excl + i < CSRW) g_csr[r * CSRW + excl + i] = lane * 32 + b;
        i++;
    }
}

// ================================================================ bulk-copy pipelined HMMA GEMM: ys = dinv * (x @ W^T) -> fp16
// CTA 128x128 (mt, half), 512 threads (16 warps 4x4), warp tile 32x32.
// Main product f32-accum; hi*lo corrections in fp16-accum mma (2x rate).
#define GSM 131072

__device__ __forceinline__ void issue_chunk(uint32_t sbuf, uint32_t mb, int mt, int hf, int c) {
    asm volatile("mbarrier.arrive.expect_tx.shared.b64 _, [%0], %1;"
                 :: "r"(mb), "r"(65536u) : "memory");
    bulk_cp(sbuf,          g_xpk + (mt * 4 + c) * 32768, 32768u, mb);
    bulk_cp(sbuf + 32768u, g_wpk + (hf * 4 + c) * 32768, 32768u, mb);
}

__global__ void __launch_bounds__(512) k_gemm()
{
    extern __shared__ __align__(128) char dsm[];
    __shared__ __align__(8) unsigned long long s_mbar[2];
    uint32_t base = s2u(dsm);
    uint32_t mbar = s2u(s_mbar);

    int tid = threadIdx.x;
    int wid = tid >> 5, lane = tid & 31;
    int g = lane >> 2, tg = lane & 3;
    int wm = wid >> 2, wn = wid & 3;
    int mt = blockIdx.x, hf = blockIdx.y;

    if (tid == 0) {
        asm volatile("mbarrier.init.shared.b64 [%0], 1;" :: "r"(mbar)     : "memory");
        asm volatile("mbarrier.init.shared.b64 [%0], 1;" :: "r"(mbar + 8) : "memory");
    }
    __syncthreads();
    if (tid == 0) {
        issue_chunk(base,          mbar,     mt, hf, 0);
        issue_chunk(base + 65536u, mbar + 8, mt, hf, 1);
    }

    uint32_t lanerow = (uint32_t)((lane & 15) * 128);
    uint32_t colbase = (uint32_t)((lane >> 4) * 16);
    uint32_t xorm    = (uint32_t)((lane & 7) << 4);

    float    acc[2][4][4];      // f32 main accumulators
    uint32_t cacc[2][4][2];     // f16x2 correction accumulators
    #pragma unroll
    for (int i = 0; i < 2; i++)
        #pragma unroll
        for (int j = 0; j < 4; j++) {
            #pragma unroll
            for (int q = 0; q < 4; q++) acc[i][j][q] = 0.f;
            cacc[i][j][0] = 0u; cacc[i][j][1] = 0u;
        }

    for (int c = 0; c < 4; c++) {
        uint32_t buf = base + (uint32_t)(c & 1) * 65536u;
        mbar_wait(mbar + (uint32_t)(c & 1) * 8, (uint32_t)(c >> 1));

        uint32_t abase = buf + (uint32_t)(wm * 32 * 128) + lanerow;           // hi; lo at +16384
        uint32_t bbase = buf + 32768u + (uint32_t)(wn * 32 * 128) + lanerow;

        #pragma unroll
        for (int ks = 0; ks < 4; ks++) {
            uint32_t koff = (colbase + (uint32_t)(ks * 32)) ^ xorm;
            uint32_t ah[2][4], al[2][4], bh[2][4], bl[2][4];
            #pragma unroll
            for (int mi = 0; mi < 2; mi++) {
                ldsm4(ah[mi], abase + (uint32_t)(mi * 2048) + koff);
                ldsm4(al[mi], abase + 16384u + (uint32_t)(mi * 2048) + koff);
            }
            #pragma unroll
            for (int nt = 0; nt < 2; nt++) {
                ldsm4(bh[nt], bbase + (uint32_t)(nt * 2048) + koff);
                ldsm4(bl[nt], bbase + 16384u + (uint32_t)(nt * 2048) + koff);
            }
            #pragma unroll
            for (int mi = 0; mi < 2; mi++)
                #pragma unroll
                for (int ni = 0; ni < 4; ni++) {
                    int nt = ni >> 1, sel = ni & 1;
                    uint32_t bbh[2] = { bh[nt][sel], bh[nt][sel + 2] };
                    uint32_t bbl[2] = { bl[nt][sel], bl[nt][sel + 2] };
                    mma_f32(acc[mi][ni], ah[mi], bbh);        // Ah*Bh (f32 accum)
                    mma_f16(cacc[mi][ni], ah[mi], bbl);       // Ah*(Bl*1024) (f16 accum)
                    mma_f16(cacc[mi][ni], al[mi], bbh);       // (Al*1024)*Bh (f16 accum)
                }
        }
        __syncthreads();                       // all warps done with this buffer
        if (c < 2 && tid == 0)
            issue_chunk(buf, mbar + (uint32_t)(c & 1) * 8, mt, hf, c + 2);
    }

    // ---- epilogue: ys = dinv[row] * (main + corr/1024), store fp16
    const float cs = 1.f / 1024.f;
    int m0 = mt * 128, n0 = hf * 128;
    #pragma unroll
    for (int mi = 0; mi < 2; mi++) {
        int r = m0 + wm * 32 + mi * 16 + g;
        float d0 = g_dinv[r];
        float d1 = g_dinv[r + 8];
        #pragma unroll
        for (int ni = 0; ni < 4; ni++) {
            int ncol = n0 + wn * 32 + ni * 8 + tg * 2;
            float2 c01 = __half22float2(*(__half2*)&cacc[mi][ni][0]);
            float2 c23 = __half22float2(*(__half2*)&cacc[mi][ni][1]);
            float o0 = (acc[mi][ni][0] + c01.x * cs) * d0;
            float o1 = (acc[mi][ni][1] + c01.y * cs) * d0;
            float o2 = (acc[mi][ni][2] + c23.x * cs) * d1;
            float o3 = (acc[mi][ni][3] + c23.y * cs) * d1;
            uint32_t p0, p1;
            asm("cvt.rn.f16x2.f32 %0, %1, %2;" : "=r"(p0) : "f"(o1), "f"(o0));
            asm("cvt.rn.f16x2.f32 %0, %1, %2;" : "=r"(p1) : "f"(o3), "f"(o2));
            *(uint32_t*)&g_ysh[r * CH + ncol]       = p0;
            *(uint32_t*)&g_ysh[(r + 8) * CH + ncol] = p1;
        }
    }
}

// ================================================================ aggregate: out = dinv_i*(Σ_N ys + ys_self) + bias
// one block (64 threads) per row; 4 fp16 channels per thread; gather unrolled x4
__global__ void __launch_bounds__(64) k_aggregate(const float* __restrict__ bias,
                                                  float* __restrict__ out)
{
    __shared__ int s_list[CSRW];

    int row   = blockIdx.x;
    int gbase = row & ~(NNODE - 1);
    int t     = threadIdx.x;

    if (t < CSRW) s_list[t] = g_csr[row * CSRW + t];
    __syncthreads();

    int   cnt  = g_cnt[row];
    float dinv = g_dinv[row];
    const uint2* ys = (const uint2*)g_ysh;          // 4 halves per uint2; row stride 64

    float4 a0, a1, a2, a3;
    {
        uint2 u = ys[row * 64 + t];                 // self (eye) term
        float2 f0 = __half22float2(*(__half2*)&u.x);
        float2 f1 = __half22float2(*(__half2*)&u.y);
        a0 = make_float4(f0.x, f0.y, f1.x, f1.y);
    }
    a1 = make_float4(0.f, 0.f, 0.f, 0.f);
    a2 = make_float4(0.f, 0.f, 0.f, 0.f);
    a3 = make_float4(0.f, 0.f, 0.f, 0.f);

    int p = 0;
    for (; p + 4 <= cnt; p += 4) {
        uint2 u0 = ys[(gbase + s_list[p])     * 64 + t];
        uint2 u1 = ys[(gbase + s_list[p + 1]) * 64 + t];
        uint2 u2 = ys[(gbase + s_list[p + 2]) * 64 + t];
        uint2 u3 = ys[(gbase + s_list[p + 3]) * 64 + t];
        float2 f;
        f = __half22float2(*(__half2*)&u0.x); a0.x += f.x; a0.y += f.y;
        f = __half22float2(*(__half2*)&u0.y); a0.z += f.x; a0.w += f.y;
        f = __half22float2(*(__half2*)&u1.x); a1.x += f.x; a1.y += f.y;
        f = __half22float2(*(__half2*)&u1.y); a1.z += f.x; a1.w += f.y;
        f = __half22float2(*(__half2*)&u2.x); a2.x += f.x; a2.y += f.y;
        f = __half22float2(*(__half2*)&u2.y); a2.z += f.x; a2.w += f.y;
        f = __half22float2(*(__half2*)&u3.x); a3.x += f.x; a3.y += f.y;
        f = __half22float2(*(__half2*)&u3.y); a3.z += f.x; a3.w += f.y;
    }
    for (; p < cnt; p++) {
        uint2 u = ys[(gbase + s_list[p]) * 64 + t];
        float2 f;
        f = __half22float2(*(__half2*)&u.x); a0.x += f.x; a0.y += f.y;
        f = __half22float2(*(__half2*)&u.y); a0.z += f.x; a0.w += f.y;
    }
    a0.x += a1.x + a2.x + a3.x;
    a0.y += a1.y + a2.y + a3.y;
    a0.z += a1.z + a2.z + a3.z;
    a0.w += a1.w + a2.w + a3.w;

    float4 bv = *(const float4*)&bias[t * 4];
    float4 o;
    o.x = fmaf(dinv, a0.x, bv.x);
    o.y = fmaf(dinv, a0.y, bv.y);
    o.z = fmaf(dinv, a0.z, bv.z);
    o.w = fmaf(dinv, a0.w, bv.w);
    *(float4*)&out[row * CH + t * 4] = o;
}

// ================================================================ launch
extern "C" void kernel_launch(void* const* d_in, const int* in_sizes, int n_in,
                              void* d_out, int out_size)
{
    const float* x    = (const float*)d_in[0];   // [8,1024,256] f32
    const int*   ei   = (const int*)  d_in[1];   // [2,16384,8] int32
    const float* Wm   = (const float*)d_in[2];   // [256,256] f32
    const float* bias = (const float*)d_in[3];   // [256] f32
    float*       out  = (float*)d_out;

    cudaFuncSetAttribute(k_gemm, cudaFuncAttributeMaxDynamicSharedMemorySize, GSM);

    k_prep<<<BIGN * 32 / 256, 256>>>(x, Wm);
    k_scatter<<<(NEDGE * BATCH + 255) / 256, 256>>>(ei);
    k_deg<<<BIGN / 8, 256>>>();
    k_gemm<<<dim3(BIGN / 128, CH / 128), 512, GSM>>>();
    k_aggregate<<<BIGN, 64>>>(bias, out);
}

// round 14
// speedup vs baseline: 1.2884x; 1.1491x over previous
#include <cuda_runtime.h>
#include <cuda_fp16.h>
#include <stdint.h>

#define BATCH   8
#define NNODE   1024
#define CH      256
#define NEDGE   16384
#define BIGN    (BATCH * NNODE)          // 8192
#define WPR     32                       // bitmap words per row
#define CSRW    48                       // padded CSR width per row (ints)

// ---- scratch (__device__ globals; allocation-free rule) ----
__device__ __align__(128) unsigned g_adj[BIGN * WPR];    // 1 MB adjacency bitmap
__device__ __align__(128) float    g_dinv[BIGN];
__device__ __align__(128) __half   g_ysh[BIGN * CH];     // ys = dinv*(x@W^T), fp16 (4 MB)
__device__ __align__(128) int      g_csr[BIGN * CSRW];
__device__ __align__(128) int      g_cnt[BIGN];
// packed fp16 tiles, SW128-swizzled, contiguous per (tile, kchunk):
// x: [64 m-tiles(128 rows)][4 chunks][hi 16KB]            -> 16KB units
// w: [2 n-halves(128 rows)][4 chunks][hi 16KB | lo 16KB]  -> 32KB units
// W lo values pre-scaled by 1024 (avoid fp16 subnormals)
__device__ __align__(128) char     g_xpk[64 * 4 * 16384];   // 4 MB
__device__ __align__(128) char     g_wpk[2 * 4 * 32768];    // 256 KB

// ================================================================ helpers
__device__ __forceinline__ uint32_t s2u(const void* p) {
    uint32_t a;
    asm("{ .reg .u64 t; cvta.to.shared.u64 t, %1; cvt.u32.u64 %0, t; }" : "=r"(a) : "l"(p));
    return a;
}
__device__ __forceinline__ uint32_t cvt2h(float2 f) {
    uint32_t h;
    asm("cvt.rn.f16x2.f32 %0, %1, %2;" : "=r"(h) : "f"(f.y), "f"(f.x));
    return h;
}
// fp16 hi/lo split; lo scaled by 1024
__device__ __forceinline__ uint32_t split2h(float2 f, uint32_t& lo) {
    uint32_t hi = cvt2h(f);
    __half2 h = *reinterpret_cast<__half2*>(&hi);
    float2 hf = __half22float2(h);
    lo = cvt2h(make_float2((f.x - hf.x) * 1024.f, (f.y - hf.y) * 1024.f));
    return hi;
}
__device__ __forceinline__ void mma_f32(float* c, const uint32_t* a, const uint32_t* b) {
    asm volatile(
        "mma.sync.aligned.m16n8k16.row.col.f32.f16.f16.f32 "
        "{%0,%1,%2,%3}, {%4,%5,%6,%7}, {%8,%9}, {%0,%1,%2,%3};"
        : "+f"(c[0]), "+f"(c[1]), "+f"(c[2]), "+f"(c[3])
        : "r"(a[0]), "r"(a[1]), "r"(a[2]), "r"(a[3]), "r"(b[0]), "r"(b[1]));
}
__device__ __forceinline__ void ldsm4(uint32_t* r, uint32_t addr) {
    asm volatile("ldmatrix.sync.aligned.m8n8.x4.shared.b16 {%0,%1,%2,%3}, [%4];"
                 : "=r"(r[0]), "=r"(r[1]), "=r"(r[2]), "=r"(r[3]) : "r"(addr));
}
__device__ __forceinline__ void mbar_wait(uint32_t addr, uint32_t parity) {
    asm volatile(
        "{\n\t.reg .pred P1;\n"
        "WL%=:\n\t"
        "mbarrier.try_wait.parity.acquire.cta.shared::cta.b64 P1, [%0], %1, 0x989680;\n\t"
        "@P1 bra WD%=;\n\t"
        "bra WL%=;\n"
        "WD%=:\n\t}"
        :: "r"(addr), "r"(parity) : "memory");
}
__device__ __forceinline__ void bulk_cp(uint32_t sdst, const void* gsrc, uint32_t bytes,
                                        uint32_t mb) {
    asm volatile(
        "{ .reg .u64 g; cvta.to.global.u64 g, %1;\n\t"
        "cp.async.bulk.shared::cta.global.mbarrier::complete_tx::bytes [%0], [g], %2, [%3]; }"
        :: "r"(sdst), "l"(gsrc), "r"(bytes), "r"(mb) : "memory");
}

// ================================================================ prep: pack x (fp16 hi) + W (fp16 hi/lo), swizzled; zero bitmap
__global__ void __launch_bounds__(256) k_prep(const float* __restrict__ x,
                                              const float* __restrict__ Wm)
{
    int t = blockIdx.x * 256 + threadIdx.x;          // 262144 threads
    {
        int row = t >> 5, s = t & 31, ch = s * 8;
        const float4* xp = (const float4*)(x + row * CH + ch);
        float4 v0 = xp[0], v1 = xp[1];
        uint4 hv;
        hv.x = cvt2h(make_float2(v0.x, v0.y));
        hv.y = cvt2h(make_float2(v0.z, v0.w));
        hv.z = cvt2h(make_float2(v1.x, v1.y));
        hv.w = cvt2h(make_float2(v1.z, v1.w));
        int tile = row >> 7, r = row & 127, c = ch >> 6, cc = ch & 63;
        uint32_t off = (uint32_t)((tile * 4 + c) * 16384)
                     + ((uint32_t)(r * 128 + cc * 2) ^ ((uint32_t)(r & 7) << 4));
        *(uint4*)(g_xpk + off) = hv;
    }
    if (t < CH * 32) {                                // 8192 threads for W
        int row = t >> 5, s = t & 31, ch = s * 8;
        const float4* wp = (const float4*)(Wm + row * CH + ch);
        float4 v0 = wp[0], v1 = wp[1];
        uint4 hv, lv;
        hv.x = split2h(make_float2(v0.x, v0.y), lv.x);
        hv.y = split2h(make_float2(v0.z, v0.w), lv.y);
        hv.z = split2h(make_float2(v1.x, v1.y), lv.z);
        hv.w = split2h(make_float2(v1.z, v1.w), lv.w);
        int hf = row >> 7, r = row & 127, c = ch >> 6, cc = ch & 63;
        uint32_t off = (uint32_t)((hf * 4 + c) * 32768)
                     + ((uint32_t)(r * 128 + cc * 2) ^ ((uint32_t)(r & 7) << 4));
        *(uint4*)(g_wpk + off)         = hv;
        *(uint4*)(g_wpk + off + 16384) = lv;
    }
    if (t < BIGN * WPR / 4)
        ((uint4*)g_adj)[t] = make_uint4(0u, 0u, 0u, 0u);
}

// ================================================================ edge scatter (dedup via bitmap)
__global__ void k_scatter(const int* __restrict__ ei) {
    int t = blockIdx.x * blockDim.x + threadIdx.x;
    if (t >= NEDGE * BATCH) return;
    int src = ei[t];
    int dst = ei[NEDGE * BATCH + t];
    int b   = t & (BATCH - 1);
    int row = b * NNODE + src;
    atomicOr(&g_adj[row * WPR + (dst >> 5)], 1u << (dst & 31));
}

// ================================================================ degree -> dinv + CSR extraction
__global__ void __launch_bounds__(256) k_deg() {
    int tid  = threadIdx.x;
    int lane = tid & 31;
    int r    = blockIdx.x * 8 + (tid >> 5);

    unsigned w = g_adj[r * WPR + lane];
    int c = __popc(w);
    int s = c;
    #pragma unroll
    for (int o = 1; o < 32; o <<= 1) {
        int v = __shfl_up_sync(0xffffffffu, s, o);
        if (lane >= o) s += v;
    }
    int excl  = s - c;
    int total = __shfl_sync(0xffffffffu, s, 31);
    if (lane == 0) {
        g_dinv[r] = rsqrtf((float)(total + 1));    // +1 self loop (eye)
        g_cnt[r]  = total;
    }
    int i = 0;
    while (w) {
        int b = __ffs(w) - 1;
        w &= w - 1;
        if (excl + i < CSRW) g_csr[r * CSRW + excl + i] = lane * 32 + b;
        i++;
    }
}

// ================================================================ 2-product HMMA GEMM: ys = dinv*(x@W^T) -> fp16
// CTA 128x128 (mt, half), 512 threads (16 warps 4x4), warp tile 32x32.
// Products: Ah*Bh (f32 acc) + Ah*(Bl*1024) (f32 acc, rescaled in epilogue).
// Chunk = [A hi 16KB][B hi 16KB][B lo 16KB] = 48KB, bulk-copied, double buffered.
#define CHUNKB 49152u
#define GSM    98304

__device__ __forceinline__ void issue_chunk(uint32_t sbuf, uint32_t mb, int mt, int hf, int c) {
    asm volatile("mbarrier.arrive.expect_tx.shared.b64 _, [%0], %1;"
                 :: "r"(mb), "r"(CHUNKB) : "memory");
    bulk_cp(sbuf,          g_xpk + (mt * 4 + c) * 16384, 16384u, mb);
    bulk_cp(sbuf + 16384u, g_wpk + (hf * 4 + c) * 32768, 32768u, mb);
}

__global__ void __launch_bounds__(512) k_gemm()
{
    extern __shared__ __align__(128) char dsm[];
    __shared__ __align__(8) unsigned long long s_mbar[2];
    uint32_t base = s2u(dsm);
    uint32_t mbar = s2u(s_mbar);

    int tid = threadIdx.x;
    int wid = tid >> 5, lane = tid & 31;
    int g = lane >> 2, tg = lane & 3;
    int wm = wid >> 2, wn = wid & 3;
    int mt = blockIdx.x, hf = blockIdx.y;

    if (tid == 0) {
        asm volatile("mbarrier.init.shared.b64 [%0], 1;" :: "r"(mbar)     : "memory");
        asm volatile("mbarrier.init.shared.b64 [%0], 1;" :: "r"(mbar + 8) : "memory");
    }
    __syncthreads();
    if (tid == 0) {
        issue_chunk(base,          mbar,     mt, hf, 0);
        issue_chunk(base + CHUNKB, mbar + 8, mt, hf, 1);
    }

    uint32_t lanerow = (uint32_t)((lane & 15) * 128);
    uint32_t colbase = (uint32_t)((lane >> 4) * 16);
    uint32_t xorm    = (uint32_t)((lane & 7) << 4);

    float acc[2][4][4];      // main accumulators (Ah*Bh)
    float cacc[2][4][4];     // correction accumulators (Ah*Bl*1024)
    #pragma unroll
    for (int i = 0; i < 2; i++)
        #pragma unroll
        for (int j = 0; j < 4; j++)
            #pragma unroll
            for (int q = 0; q < 4; q++) { acc[i][j][q] = 0.f; cacc[i][j][q] = 0.f; }

    for (int c = 0; c < 4; c++) {
        uint32_t buf = base + (uint32_t)(c & 1) * CHUNKB;
        mbar_wait(mbar + (uint32_t)(c & 1) * 8, (uint32_t)(c >> 1));

        uint32_t abase = buf + (uint32_t)(wm * 32 * 128) + lanerow;
        uint32_t bbase = buf + 16384u + (uint32_t)(wn * 32 * 128) + lanerow;  // hi; lo at +16384

        #pragma unroll
        for (int ks = 0; ks < 4; ks++) {
            uint32_t koff = (colbase + (uint32_t)(ks * 32)) ^ xorm;
            uint32_t ah[2][4], bh[2][4], bl[2][4];
            #pragma unroll
            for (int mi = 0; mi < 2; mi++)
                ldsm4(ah[mi], abase + (uint32_t)(mi * 2048) + koff);
            #pragma unroll
            for (int nt = 0; nt < 2; nt++) {
                ldsm4(bh[nt], bbase + (uint32_t)(nt * 2048) + koff);
                ldsm4(bl[nt], bbase + 16384u + (uint32_t)(nt * 2048) + koff);
            }
            #pragma unroll
            for (int mi = 0; mi < 2; mi++)
                #pragma unroll
                for (int ni = 0; ni < 4; ni++) {
                    int nt = ni >> 1, sel = ni & 1;
                    uint32_t bbh[2] = { bh[nt][sel], bh[nt][sel + 2] };
                    uint32_t bbl[2] = { bl[nt][sel], bl[nt][sel + 2] };
                    mma_f32(acc[mi][ni],  ah[mi], bbh);
                    mma_f32(cacc[mi][ni], ah[mi], bbl);
                }
        }
        __syncthreads();                       // all warps done with this buffer
        if (c < 2 && tid == 0)
            issue_chunk(buf, mbar + (uint32_t)(c & 1) * 8, mt, hf, c + 2);
    }

    // ---- epilogue: ys = dinv[row] * (main + corr/1024), store fp16
    const float cs = 1.f / 1024.f;
    int m0 = mt * 128, n0 = hf * 128;
    #pragma unroll
    for (int mi = 0; mi < 2; mi++) {
        int r = m0 + wm * 32 + mi * 16 + g;
        float d0 = g_dinv[r];
        float d1 = g_dinv[r + 8];
        #pragma unroll
        for (int ni = 0; ni < 4; ni++) {
            int ncol = n0 + wn * 32 + ni * 8 + tg * 2;
            float o0 = fmaf(cacc[mi][ni][0], cs, acc[mi][ni][0]) * d0;
            float o1 = fmaf(cacc[mi][ni][1], cs, acc[mi][ni][1]) * d0;
            float o2 = fmaf(cacc[mi][ni][2], cs, acc[mi][ni][2]) * d1;
            float o3 = fmaf(cacc[mi][ni][3], cs, acc[mi][ni][3]) * d1;
            *(uint32_t*)&g_ysh[r * CH + ncol]       = cvt2h(make_float2(o0, o1));
            *(uint32_t*)&g_ysh[(r + 8) * CH + ncol] = cvt2h(make_float2(o2, o3));
        }
    }
}

// ================================================================ aggregate: out = dinv_i*(Σ_N ys + ys_self) + bias
// one block (64 threads) per row; 4 fp16 channels per thread; gather unrolled x4
__global__ void __launch_bounds__(64) k_aggregate(const float* __restrict__ bias,
                                                  float* __restrict__ out)
{
    __shared__ int s_list[CSRW];

    int row   = blockIdx.x;
    int gbase = row & ~(NNODE - 1);
    int t     = threadIdx.x;

    if (t < CSRW) s_list[t] = g_csr[row * CSRW + t];
    __syncthreads();

    int   cnt  = g_cnt[row];
    float dinv = g_dinv[row];
    const uint2* ys = (const uint2*)g_ysh;          // 4 halves per uint2; row stride 64

    float4 a0, a1, a2, a3;
    {
        uint2 u = ys[row * 64 + t];                 // self (eye) term
        float2 f0 = __half22float2(*(__half2*)&u.x);
        float2 f1 = __half22float2(*(__half2*)&u.y);
        a0 = make_float4(f0.x, f0.y, f1.x, f1.y);
    }
    a1 = make_float4(0.f, 0.f, 0.f, 0.f);
    a2 = make_float4(0.f, 0.f, 0.f, 0.f);
    a3 = make_float4(0.f, 0.f, 0.f, 0.f);

    int p = 0;
    for (; p + 4 <= cnt; p += 4) {
        uint2 u0 = ys[(gbase + s_list[p])     * 64 + t];
        uint2 u1 = ys[(gbase + s_list[p + 1]) * 64 + t];
        uint2 u2 = ys[(gbase + s_list[p + 2]) * 64 + t];
        uint2 u3 = ys[(gbase + s_list[p + 3]) * 64 + t];
        float2 f;
        f = __half22float2(*(__half2*)&u0.x); a0.x += f.x; a0.y += f.y;
        f = __half22float2(*(__half2*)&u0.y); a0.z += f.x; a0.w += f.y;
        f = __half22float2(*(__half2*)&u1.x); a1.x += f.x; a1.y += f.y;
        f = __half22float2(*(__half2*)&u1.y); a1.z += f.x; a1.w += f.y;
        f = __half22float2(*(__half2*)&u2.x); a2.x += f.x; a2.y += f.y;
        f = __half22float2(*(__half2*)&u2.y); a2.z += f.x; a2.w += f.y;
        f = __half22float2(*(__half2*)&u3.x); a3.x += f.x; a3.y += f.y;
        f = __half22float2(*(__half2*)&u3.y); a3.z += f.x; a3.w += f.y;
    }
    for (; p < cnt; p++) {
        uint2 u = ys[(gbase + s_list[p]) * 64 + t];
        float2 f;
        f = __half22float2(*(__half2*)&u.x); a0.x += f.x; a0.y += f.y;
        f = __half22float2(*(__half2*)&u.y); a0.z += f.x; a0.w += f.y;
    }
    a0.x += a1.x + a2.x + a3.x;
    a0.y += a1.y + a2.y + a3.y;
    a0.z += a1.z + a2.z + a3.z;
    a0.w += a1.w + a2.w + a3.w;

    float4 bv = *(const float4*)&bias[t * 4];
    float4 o;
    o.x = fmaf(dinv, a0.x, bv.x);
    o.y = fmaf(dinv, a0.y, bv.y);
    o.z = fmaf(dinv, a0.z, bv.z);
    o.w = fmaf(dinv, a0.w, bv.w);
    *(float4*)&out[row * CH + t * 4] = o;
}

// ================================================================ launch
extern "C" void kernel_launch(void* const* d_in, const int* in_sizes, int n_in,
                              void* d_out, int out_size)
{
    const float* x    = (const float*)d_in[0];   // [8,1024,256] f32
    const int*   ei   = (const int*)  d_in[1];   // [2,16384,8] int32
    const float* Wm   = (const float*)d_in[2];   // [256,256] f32
    const float* bias = (const float*)d_in[3];   // [256] f32
    float*       out  = (float*)d_out;

    cudaFuncSetAttribute(k_gemm, cudaFuncAttributeMaxDynamicSharedMemorySize, GSM);

    k_prep<<<BIGN * 32 / 256, 256>>>(x, Wm);
    k_scatter<<<(NEDGE * BATCH + 255) / 256, 256>>>(ei);
    k_deg<<<BIGN / 8, 256>>>();
    k_gemm<<<dim3(BIGN / 128, CH / 128), 512, GSM>>>();
    k_aggregate<<<BIGN, 64>>>(bias, out);
}

// round 15
// speedup vs baseline: 1.3600x; 1.0556x over previous
#include <cuda_runtime.h>
#include <cuda_fp16.h>
#include <stdint.h>

#define BATCH   8
#define NNODE   1024
#define CH      256
#define NEDGE   16384
#define BIGN    (BATCH * NNODE)          // 8192
#define WPR     32                       // bitmap words per row
#define CSRW    48                       // padded CSR width per row (ints)

// ---- scratch (__device__ globals; allocation-free rule) ----
__device__ __align__(128) unsigned g_adj[BIGN * WPR];    // 1 MB adjacency bitmap
__device__ __align__(128) float    g_dinv[BIGN];
__device__ __align__(128) __half   g_ysh[BIGN * CH];     // ys = dinv*(x@W^T), fp16 (4 MB)
__device__ __align__(128) int      g_csr[BIGN * CSRW];
__device__ __align__(128) int      g_cnt[BIGN];
// packed fp16 tiles, SW128-swizzled, contiguous per (tile, kchunk):
// x: [64 m-tiles(128 rows)][4 chunks][16KB]
// w: [2 n-halves(128 rows)][4 chunks][16KB]
__device__ __align__(128) char     g_xpk[64 * 4 * 16384];   // 4 MB
__device__ __align__(128) char     g_wpk[2 * 4 * 16384];    // 128 KB

// ================================================================ helpers
__device__ __forceinline__ uint32_t s2u(const void* p) {
    uint32_t a;
    asm("{ .reg .u64 t; cvta.to.shared.u64 t, %1; cvt.u32.u64 %0, t; }" : "=r"(a) : "l"(p));
    return a;
}
__device__ __forceinline__ uint32_t cvt2h(float2 f) {
    uint32_t h;
    asm("cvt.rn.f16x2.f32 %0, %1, %2;" : "=r"(h) : "f"(f.y), "f"(f.x));
    return h;
}
__device__ __forceinline__ void mma_f32(float* c, const uint32_t* a, const uint32_t* b) {
    asm volatile(
        "mma.sync.aligned.m16n8k16.row.col.f32.f16.f16.f32 "
        "{%0,%1,%2,%3}, {%4,%5,%6,%7}, {%8,%9}, {%0,%1,%2,%3};"
        : "+f"(c[0]), "+f"(c[1]), "+f"(c[2]), "+f"(c[3])
        : "r"(a[0]), "r"(a[1]), "r"(a[2]), "r"(a[3]), "r"(b[0]), "r"(b[1]));
}
__device__ __forceinline__ void ldsm4(uint32_t* r, uint32_t addr) {
    asm volatile("ldmatrix.sync.aligned.m8n8.x4.shared.b16 {%0,%1,%2,%3}, [%4];"
                 : "=r"(r[0]), "=r"(r[1]), "=r"(r[2]), "=r"(r[3]) : "r"(addr));
}
__device__ __forceinline__ void mbar_wait(uint32_t addr, uint32_t parity) {
    asm volatile(
        "{\n\t.reg .pred P1;\n"
        "WL%=:\n\t"
        "mbarrier.try_wait.parity.acquire.cta.shared::cta.b64 P1, [%0], %1, 0x989680;\n\t"
        "@P1 bra WD%=;\n\t"
        "bra WL%=;\n"
        "WD%=:\n\t}"
        :: "r"(addr), "r"(parity) : "memory");
}
__device__ __forceinline__ void bulk_cp(uint32_t sdst, const void* gsrc, uint32_t bytes,
                                        uint32_t mb) {
    asm volatile(
        "{ .reg .u64 g; cvta.to.global.u64 g, %1;\n\t"
        "cp.async.bulk.shared::cta.global.mbarrier::complete_tx::bytes [%0], [g], %2, [%3]; }"
        :: "r"(sdst), "l"(gsrc), "r"(bytes), "r"(mb) : "memory");
}

// ================================================================ prep: pack x,W (fp16, swizzled) + zero bitmap
__global__ void __launch_bounds__(256) k_prep(const float* __restrict__ x,
                                              const float* __restrict__ Wm)
{
    int t = blockIdx.x * 256 + threadIdx.x;          // 262144 threads
    {
        int row = t >> 5, s = t & 31, ch = s * 8;
        const float4* xp = (const float4*)(x + row * CH + ch);
        float4 v0 = xp[0], v1 = xp[1];
        uint4 hv;
        hv.x = cvt2h(make_float2(v0.x, v0.y));
        hv.y = cvt2h(make_float2(v0.z, v0.w));
        hv.z = cvt2h(make_float2(v1.x, v1.y));
        hv.w = cvt2h(make_float2(v1.z, v1.w));
        int tile = row >> 7, r = row & 127, c = ch >> 6, cc = ch & 63;
        uint32_t off = (uint32_t)((tile * 4 + c) * 16384)
                     + ((uint32_t)(r * 128 + cc * 2) ^ ((uint32_t)(r & 7) << 4));
        *(uint4*)(g_xpk + off) = hv;
    }
    if (t < CH * 32) {                                // 8192 threads for W
        int row = t >> 5, s = t & 31, ch = s * 8;
        const float4* wp = (const float4*)(Wm + row * CH + ch);
        float4 v0 = wp[0], v1 = wp[1];
        uint4 hv;
        hv.x = cvt2h(make_float2(v0.x, v0.y));
        hv.y = cvt2h(make_float2(v0.z, v0.w));
        hv.z = cvt2h(make_float2(v1.x, v1.y));
        hv.w = cvt2h(make_float2(v1.z, v1.w));
        int hf = row >> 7, r = row & 127, c = ch >> 6, cc = ch & 63;
        uint32_t off = (uint32_t)((hf * 4 + c) * 16384)
                     + ((uint32_t)(r * 128 + cc * 2) ^ ((uint32_t)(r & 7) << 4));
        *(uint4*)(g_wpk + off) = hv;
    }
    if (t < BIGN * WPR / 4)
        ((uint4*)g_adj)[t] = make_uint4(0u, 0u, 0u, 0u);
}

// ================================================================ edge scatter (dedup via bitmap)
__global__ void k_scatter(const int* __restrict__ ei) {
    int t = blockIdx.x * blockDim.x + threadIdx.x;
    if (t >= NEDGE * BATCH) return;
    int src = ei[t];
    int dst = ei[NEDGE * BATCH + t];
    int b   = t & (BATCH - 1);
    int row = b * NNODE + src;
    atomicOr(&g_adj[row * WPR + (dst >> 5)], 1u << (dst & 31));
}

// ================================================================ degree -> dinv + CSR extraction
__global__ void __launch_bounds__(256) k_deg() {
    int tid  = threadIdx.x;
    int lane = tid & 31;
    int r    = blockIdx.x * 8 + (tid >> 5);

    unsigned w = g_adj[r * WPR + lane];
    int c = __popc(w);
    int s = c;
    #pragma unroll
    for (int o = 1; o < 32; o <<= 1) {
        int v = __shfl_up_sync(0xffffffffu, s, o);
        if (lane >= o) s += v;
    }
    int excl  = s - c;
    int total = __shfl_sync(0xffffffffu, s, 31);
    if (lane == 0) {
        g_dinv[r] = rsqrtf((float)(total + 1));    // +1 self loop (eye)
        g_cnt[r]  = total;
    }
    int i = 0;
    while (w) {
        int b = __ffs(w) - 1;
        w &= w - 1;
        if (excl + i < CSRW) g_csr[r * CSRW + excl + i] = lane * 32 + b;
        i++;
    }
}

// ================================================================ 1-product HMMA GEMM: ys = dinv*(x@W^T) -> fp16
// CTA 128x128 (mt, half), 512 threads (16 warps 4x4), warp tile 32x32.
// Chunk = [A 16KB][B 16KB] = 32KB, bulk-copied, double buffered.
#define CHUNKB 32768u
#define GSM    65536

__device__ __forceinline__ void issue_chunk(uint32_t sbuf, uint32_t mb, int mt, int hf, int c) {
    asm volatile("mbarrier.arrive.expect_tx.shared.b64 _, [%0], %1;"
                 :: "r"(mb), "r"(CHUNKB) : "memory");
    bulk_cp(sbuf,          g_xpk + (mt * 4 + c) * 16384, 16384u, mb);
    bulk_cp(sbuf + 16384u, g_wpk + (hf * 4 + c) * 16384, 16384u, mb);
}

__global__ void __launch_bounds__(512) k_gemm()
{
    extern __shared__ __align__(128) char dsm[];
    __shared__ __align__(8) unsigned long long s_mbar[2];
    uint32_t base = s2u(dsm);
    uint32_t mbar = s2u(s_mbar);

    int tid = threadIdx.x;
    int wid = tid >> 5, lane = tid & 31;
    int g = lane >> 2, tg = lane & 3;
    int wm = wid >> 2, wn = wid & 3;
    int mt = blockIdx.x, hf = blockIdx.y;

    if (tid == 0) {
        asm volatile("mbarrier.init.shared.b64 [%0], 1;" :: "r"(mbar)     : "memory");
        asm volatile("mbarrier.init.shared.b64 [%0], 1;" :: "r"(mbar + 8) : "memory");
    }
    __syncthreads();
    if (tid == 0) {
        issue_chunk(base,          mbar,     mt, hf, 0);
        issue_chunk(base + CHUNKB, mbar + 8, mt, hf, 1);
    }

    uint32_t lanerow = (uint32_t)((lane & 15) * 128);
    uint32_t colbase = (uint32_t)((lane >> 4) * 16);
    uint32_t xorm    = (uint32_t)((lane & 7) << 4);

    float acc[2][4][4];
    #pragma unroll
    for (int i = 0; i < 2; i++)
        #pragma unroll
        for (int j = 0; j < 4; j++)
            #pragma unroll
            for (int q = 0; q < 4; q++) acc[i][j][q] = 0.f;

    for (int c = 0; c < 4; c++) {
        uint32_t buf = base + (uint32_t)(c & 1) * CHUNKB;
        mbar_wait(mbar + (uint32_t)(c & 1) * 8, (uint32_t)(c >> 1));

        uint32_t abase = buf + (uint32_t)(wm * 32 * 128) + lanerow;
        uint32_t bbase = buf + 16384u + (uint32_t)(wn * 32 * 128) + lanerow;

        #pragma unroll
        for (int ks = 0; ks < 4; ks++) {
            uint32_t koff = (colbase + (uint32_t)(ks * 32)) ^ xorm;
            uint32_t ah[2][4], bh[2][4];
            #pragma unroll
            for (int mi = 0; mi < 2; mi++)
                ldsm4(ah[mi], abase + (uint32_t)(mi * 2048) + koff);
            #pragma unroll
            for (int nt = 0; nt < 2; nt++)
                ldsm4(bh[nt], bbase + (uint32_t)(nt * 2048) + koff);
            #pragma unroll
            for (int mi = 0; mi < 2; mi++)
                #pragma unroll
                for (int ni = 0; ni < 4; ni++) {
                    int nt = ni >> 1, sel = ni & 1;
                    uint32_t bb[2] = { bh[nt][sel], bh[nt][sel + 2] };
                    mma_f32(acc[mi][ni], ah[mi], bb);
                }
        }
        __syncthreads();                       // all warps done with this buffer
        if (c < 2 && tid == 0)
            issue_chunk(buf, mbar + (uint32_t)(c & 1) * 8, mt, hf, c + 2);
    }

    // ---- epilogue: ys = dinv[row] * acc, store fp16
    int m0 = mt * 128, n0 = hf * 128;
    #pragma unroll
    for (int mi = 0; mi < 2; mi++) {
        int r = m0 + wm * 32 + mi * 16 + g;
        float d0 = g_dinv[r];
        float d1 = g_dinv[r + 8];
        #pragma unroll
        for (int ni = 0; ni < 4; ni++) {
            int ncol = n0 + wn * 32 + ni * 8 + tg * 2;
            float o0 = acc[mi][ni][0] * d0;
            float o1 = acc[mi][ni][1] * d0;
            float o2 = acc[mi][ni][2] * d1;
            float o3 = acc[mi][ni][3] * d1;
            *(uint32_t*)&g_ysh[r * CH + ncol]       = cvt2h(make_float2(o0, o1));
            *(uint32_t*)&g_ysh[(r + 8) * CH + ncol] = cvt2h(make_float2(o2, o3));
        }
    }
}

// ================================================================ aggregate: out = dinv_i*(Σ_N ys + ys_self) + bias
// one block (64 threads) per row; 4 fp16 channels per thread; gather unrolled x4
__global__ void __launch_bounds__(64) k_aggregate(const float* __restrict__ bias,
                                                  float* __restrict__ out)
{
    __shared__ int s_list[CSRW];

    int row   = blockIdx.x;
    int gbase = row & ~(NNODE - 1);
    int t     = threadIdx.x;

    if (t < CSRW) s_list[t] = g_csr[row * CSRW + t];
    __syncthreads();

    int   cnt  = g_cnt[row];
    float dinv = g_dinv[row];
    const uint2* ys = (const uint2*)g_ysh;          // 4 halves per uint2; row stride 64

    float4 a0, a1, a2, a3;
    {
        uint2 u = ys[row * 64 + t];                 // self (eye) term
        float2 f0 = __half22float2(*(__half2*)&u.x);
        float2 f1 = __half22float2(*(__half2*)&u.y);
        a0 = make_float4(f0.x, f0.y, f1.x, f1.y);
    }
    a1 = make_float4(0.f, 0.f, 0.f, 0.f);
    a2 = make_float4(0.f, 0.f, 0.f, 0.f);
    a3 = make_float4(0.f, 0.f, 0.f, 0.f);

    int p = 0;
    for (; p + 4 <= cnt; p += 4) {
        uint2 u0 = ys[(gbase + s_list[p])     * 64 + t];
        uint2 u1 = ys[(gbase + s_list[p + 1]) * 64 + t];
        uint2 u2 = ys[(gbase + s_list[p + 2]) * 64 + t];
        uint2 u3 = ys[(gbase + s_list[p + 3]) * 64 + t];
        float2 f;
        f = __half22float2(*(__half2*)&u0.x); a0.x += f.x; a0.y += f.y;
        f = __half22float2(*(__half2*)&u0.y); a0.z += f.x; a0.w += f.y;
        f = __half22float2(*(__half2*)&u1.x); a1.x += f.x; a1.y += f.y;
        f = __half22float2(*(__half2*)&u1.y); a1.z += f.x; a1.w += f.y;
        f = __half22float2(*(__half2*)&u2.x); a2.x += f.x; a2.y += f.y;
        f = __half22float2(*(__half2*)&u2.y); a2.z += f.x; a2.w += f.y;
        f = __half22float2(*(__half2*)&u3.x); a3.x += f.x; a3.y += f.y;
        f = __half22float2(*(__half2*)&u3.y); a3.z += f.x; a3.w += f.y;
    }
    for (; p < cnt; p++) {
        uint2 u = ys[(gbase + s_list[p]) * 64 + t];
        float2 f;
        f = __half22float2(*(__half2*)&u.x); a0.x += f.x; a0.y += f.y;
        f = __half22float2(*(__half2*)&u.y); a0.z += f.x; a0.w += f.y;
    }
    a0.x += a1.x + a2.x + a3.x;
    a0.y += a1.y + a2.y + a3.y;
    a0.z += a1.z + a2.z + a3.z;
    a0.w += a1.w + a2.w + a3.w;

    float4 bv = *(const float4*)&bias[t * 4];
    float4 o;
    o.x = fmaf(dinv, a0.x, bv.x);
    o.y = fmaf(dinv, a0.y, bv.y);
    o.z = fmaf(dinv, a0.z, bv.z);
    o.w = fmaf(dinv, a0.w, bv.w);
    *(float4*)&out[row * CH + t * 4] = o;
}

// ================================================================ launch
extern "C" void kernel_launch(void* const* d_in, const int* in_sizes, int n_in,
                              void* d_out, int out_size)
{
    const float* x    = (const float*)d_in[0];   // [8,1024,256] f32
    const int*   ei   = (const int*)  d_in[1];   // [2,16384,8] int32
    const float* Wm   = (const float*)d_in[2];   // [256,256] f32
    const float* bias = (const float*)d_in[3];   // [256] f32
    float*       out  = (float*)d_out;

    cudaFuncSetAttribute(k_gemm, cudaFuncAttributeMaxDynamicSharedMemorySize, GSM);

    k_prep<<<BIGN * 32 / 256, 256>>>(x, Wm);
    k_scatter<<<(NEDGE * BATCH + 255) / 256, 256>>>(ei);
    k_deg<<<BIGN / 8, 256>>>();
    k_gemm<<<dim3(BIGN / 128, CH / 128), 512, GSM>>>();
    k_aggregate<<<BIGN, 64>>>(bias, out);
}